// round 1
// baseline (speedup 1.0000x reference)
#include <cuda_runtime.h>

#define IMG_H 1024
#define IMG_W 768
#define IMG_C 3
#define IMG_HW (IMG_H * IMG_W)

__global__ __launch_bounds__(256) void warp_kernel(
    const float* __restrict__ image,
    const float* __restrict__ flow,
    float* __restrict__ out,
    int nquads)
{
    int i = blockIdx.x * blockDim.x + threadIdx.x;
    if (i >= nquads) return;

    int p0 = i * 4;                    // first pixel of this quad
    int b   = p0 / IMG_HW;
    int rem = p0 - b * IMG_HW;
    int y   = rem / IMG_W;
    int x0  = rem - y * IMG_W;         // quad stays in one row (W % 4 == 0)

    // flow: 4 pixels * 2 floats = 8 floats = 2 aligned float4
    const float4* flow4 = (const float4*)flow;
    float4 f0 = __ldg(flow4 + (size_t)i * 2);
    float4 f1 = __ldg(flow4 + (size_t)i * 2 + 1);
    float dy[4] = {f0.x, f0.z, f1.x, f1.z};
    float dx[4] = {f0.y, f0.w, f1.y, f1.w};

    const float* imgb = image + (size_t)b * IMG_HW * IMG_C;

    float r[12];
    #pragma unroll
    for (int k = 0; k < 4; k++) {
        float qy = (float)y        - dy[k];
        float qx = (float)(x0 + k) - dx[k];

        float y0f = fminf(fmaxf(floorf(qy), 0.0f), (float)(IMG_H - 2));
        float x0f = fminf(fmaxf(floorf(qx), 0.0f), (float)(IMG_W - 2));
        float ay  = fminf(fmaxf(qy - y0f, 0.0f), 1.0f);
        float ax  = fminf(fmaxf(qx - x0f, 0.0f), 1.0f);

        int yi = (int)y0f;
        int xi = (int)x0f;

        const float* top = imgb + ((size_t)yi * IMG_W + xi) * IMG_C;
        const float* bot = top + (size_t)IMG_W * IMG_C;

        #pragma unroll
        for (int c = 0; c < 3; c++) {
            float tl = __ldg(top + c);
            float tr = __ldg(top + c + 3);
            float bl = __ldg(bot + c);
            float br = __ldg(bot + c + 3);
            float t  = tl + ax * (tr - tl);
            float bm = bl + ax * (br - bl);
            r[k * 3 + c] = t + ay * (bm - t);
        }
    }

    // 12 contiguous floats, base offset p0*3*4 = 48*i bytes -> 16B aligned
    float4* o = (float4*)(out + (size_t)p0 * 3);
    o[0] = make_float4(r[0], r[1], r[2],  r[3]);
    o[1] = make_float4(r[4], r[5], r[6],  r[7]);
    o[2] = make_float4(r[8], r[9], r[10], r[11]);
}

extern "C" void kernel_launch(void* const* d_in, const int* in_sizes, int n_in,
                              void* d_out, int out_size) {
    const float* image = (const float*)d_in[0];
    const float* flow  = (const float*)d_in[1];
    float* out = (float*)d_out;

    int npix   = in_sizes[1] / 2;   // flow has 2 floats per pixel
    int nquads = npix / 4;

    int threads = 256;
    int blocks  = (nquads + threads - 1) / threads;
    warp_kernel<<<blocks, threads>>>(image, flow, out, nquads);
}

// round 3
// speedup vs baseline: 1.1624x; 1.1624x over previous
#include <cuda_runtime.h>

#define IMG_H 1024
#define IMG_W 768
#define IMG_C 3
#define IMG_HW (IMG_H * IMG_W)
#define ROW_F4 ((IMG_W * IMG_C) / 4)   // 576 float4 per image row

// Fetch 6 contiguous floats starting at float-offset af (phase o = af & 3)
// using two aligned LDG.128 plus one predicated scalar for o==3.
// p points at the aligned float4 containing float (af & ~3).
__device__ __forceinline__ void gather6(const float4* __restrict__ p, int o,
                                        float s[6]) {
    float4 b0 = __ldg(p);
    float4 b1 = __ldg(p + 1);
    float b2 = 0.0f;
    if (o == 3) b2 = __ldg((const float*)(p + 2));   // exactly float af+5
    switch (o) {
    case 0:  s[0]=b0.x; s[1]=b0.y; s[2]=b0.z; s[3]=b0.w; s[4]=b1.x; s[5]=b1.y; break;
    case 1:  s[0]=b0.y; s[1]=b0.z; s[2]=b0.w; s[3]=b1.x; s[4]=b1.y; s[5]=b1.z; break;
    case 2:  s[0]=b0.z; s[1]=b0.w; s[2]=b1.x; s[3]=b1.y; s[4]=b1.z; s[5]=b1.w; break;
    default: s[0]=b0.w; s[1]=b1.x; s[2]=b1.y; s[3]=b1.z; s[4]=b1.w; s[5]=b2;  break;
    }
}

__global__ __launch_bounds__(256) void warp_kernel(
    const float* __restrict__ image,
    const float* __restrict__ flow,
    float* __restrict__ out,
    int nquads)
{
    int i = blockIdx.x * blockDim.x + threadIdx.x;
    if (i >= nquads) return;

    int p0  = i * 4;                   // first pixel of this quad
    int b   = p0 / IMG_HW;
    int rem = p0 - b * IMG_HW;
    int y   = rem / IMG_W;
    int x0  = rem - y * IMG_W;         // quad stays in one row (W % 4 == 0)

    // flow: 4 pixels * 2 floats = 2 aligned float4 (perfectly coalesced)
    const float4* flow4 = (const float4*)flow;
    float4 f0 = __ldg(flow4 + (size_t)i * 2);
    float4 f1 = __ldg(flow4 + (size_t)i * 2 + 1);
    float dy[4] = {f0.x, f0.z, f1.x, f1.z};
    float dx[4] = {f0.y, f0.w, f1.y, f1.w};

    const float* imgb = image + (size_t)b * IMG_HW * IMG_C;

    float r[12];
    #pragma unroll
    for (int k = 0; k < 4; k++) {
        float qy = (float)y        - dy[k];
        float qx = (float)(x0 + k) - dx[k];

        float y0f = fminf(fmaxf(floorf(qy), 0.0f), (float)(IMG_H - 2));
        float x0f = fminf(fmaxf(floorf(qx), 0.0f), (float)(IMG_W - 2));
        float ay  = fminf(fmaxf(qy - y0f, 0.0f), 1.0f);
        float ax  = fminf(fmaxf(qx - x0f, 0.0f), 1.0f);

        int yi = (int)y0f;
        int xi = (int)x0f;

        int af = (yi * IMG_W + xi) * IMG_C;   // float offset of tl (top span)
        int o  = af & 3;                      // shared phase: row stride 2304 ≡ 0 (mod 4)
        const float4* pt = (const float4*)(imgb + (af & ~3));
        const float4* pb = pt + ROW_F4;       // bottom span, same phase

        float st[6], sb[6];
        gather6(pt, o, st);
        gather6(pb, o, sb);

        #pragma unroll
        for (int c = 0; c < 3; c++) {
            float t  = st[c] + ax * (st[c + 3] - st[c]);
            float bo = sb[c] + ax * (sb[c + 3] - sb[c]);
            r[k * 3 + c] = t + ay * (bo - t);
        }
    }

    // 12 contiguous floats, base offset p0*3*4 = 48*i bytes -> 16B aligned
    float4* o4 = (float4*)(out + (size_t)p0 * 3);
    o4[0] = make_float4(r[0], r[1], r[2],  r[3]);
    o4[1] = make_float4(r[4], r[5], r[6],  r[7]);
    o4[2] = make_float4(r[8], r[9], r[10], r[11]);
}

extern "C" void kernel_launch(void* const* d_in, const int* in_sizes, int n_in,
                              void* d_out, int out_size) {
    const float* image = (const float*)d_in[0];
    const float* flow  = (const float*)d_in[1];
    float* out = (float*)d_out;

    int npix   = in_sizes[1] / 2;   // flow has 2 floats per pixel
    int nquads = npix / 4;

    int threads = 256;
    int blocks  = (nquads + threads - 1) / threads;
    warp_kernel<<<blocks, threads>>>(image, flow, out, nquads);
}

// round 4
// speedup vs baseline: 1.4218x; 1.2231x over previous
#include <cuda_runtime.h>

#define IMG_H 1024
#define IMG_W 768
#define IMG_C 3
#define IMG_HW (IMG_H * IMG_W)
#define ROW_F4 ((IMG_W * IMG_C) / 4)   // 576 float4 per image row

// branchless 4-way select by o in {0,1,2,3}
__device__ __forceinline__ float sel4(float a, float b, float c, float d, int o) {
    float r = (o == 1) ? b : a;
    r = (o == 2) ? c : r;
    r = (o == 3) ? d : r;
    return r;
}

__global__ __launch_bounds__(256) void warp_kernel(
    const float* __restrict__ image,
    const float* __restrict__ flow,
    float* __restrict__ out)
{
    __shared__ float sbuf[256 * 3];    // 3 KB staging for coalesced stores

    int tid = threadIdx.x;
    int idx = blockIdx.x * 256 + tid;  // one pixel per thread, grid is exact

    int b   = idx / IMG_HW;
    int rem = idx - b * IMG_HW;
    int y   = rem / IMG_W;
    int x   = rem - y * IMG_W;

    float2 f = __ldg((const float2*)flow + idx);   // coalesced LDG.64
    float qy = (float)y - f.x;
    float qx = (float)x - f.y;

    float y0f = fminf(fmaxf(floorf(qy), 0.0f), (float)(IMG_H - 2));
    float x0f = fminf(fmaxf(floorf(qx), 0.0f), (float)(IMG_W - 2));
    float ay  = fminf(fmaxf(qy - y0f, 0.0f), 1.0f);
    float ax  = fminf(fmaxf(qx - x0f, 0.0f), 1.0f);

    int yi = (int)y0f;
    int xi = (int)x0f;

    const float* imgb = image + (size_t)b * (IMG_HW * IMG_C);
    int af = (yi * IMG_W + xi) * IMG_C;     // float offset of top-left sample
    int o  = af & 3;                        // phase (same for top & bottom rows)

    const float4* pt = (const float4*)(imgb + (af & ~3));
    const float4* pb = pt + ROW_F4;

    float4 t0 = __ldg(pt);
    float4 t1 = __ldg(pt + 1);
    float4 b0 = __ldg(pb);
    float4 b1 = __ldg(pb + 1);
    float t8 = 0.0f, b8 = 0.0f;
    if (o == 3) {                           // predicated, 1/4 of threads
        t8 = __ldg((const float*)(pt + 2));
        b8 = __ldg((const float*)(pb + 2));
    }

    // vertical lerp across the whole 9-float window
    float m0 = t0.x + ay * (b0.x - t0.x);
    float m1 = t0.y + ay * (b0.y - t0.y);
    float m2 = t0.z + ay * (b0.z - t0.z);
    float m3 = t0.w + ay * (b0.w - t0.w);
    float m4 = t1.x + ay * (b1.x - t1.x);
    float m5 = t1.y + ay * (b1.y - t1.y);
    float m6 = t1.z + ay * (b1.z - t1.z);
    float m7 = t1.w + ay * (b1.w - t1.w);
    float m8 = t8   + ay * (b8   - t8);

    // select left (m[o+c]) and right (m[o+3+c]) taps, horizontal lerp
    float l0 = sel4(m0, m1, m2, m3, o);
    float l1 = sel4(m1, m2, m3, m4, o);
    float l2 = sel4(m2, m3, m4, m5, o);
    float r0 = sel4(m3, m4, m5, m6, o);
    float r1 = sel4(m4, m5, m6, m7, o);
    float r2 = sel4(m5, m6, m7, m8, o);

    sbuf[tid * 3 + 0] = l0 + ax * (r0 - l0);   // bank-conflict-free (gcd(3,32)=1)
    sbuf[tid * 3 + 1] = l1 + ax * (r1 - l1);
    sbuf[tid * 3 + 2] = l2 + ax * (r2 - l2);

    __syncthreads();

    // 256 px * 12B = 3072B = 192 float4, perfectly coalesced
    if (tid < 192) {
        float4* ob = (float4*)(out + (size_t)blockIdx.x * (256 * 3));
        ob[tid] = ((const float4*)sbuf)[tid];
    }
}

extern "C" void kernel_launch(void* const* d_in, const int* in_sizes, int n_in,
                              void* d_out, int out_size) {
    const float* image = (const float*)d_in[0];
    const float* flow  = (const float*)d_in[1];
    float* out = (float*)d_out;

    int npix   = in_sizes[1] / 2;        // 18,874,368 — divisible by 256
    int blocks = npix / 256;             // 73728, no tail
    warp_kernel<<<blocks, 256>>>(image, flow, out);
}

// round 5
// speedup vs baseline: 1.4346x; 1.0090x over previous
#include <cuda_runtime.h>

#define IMG_H 1024
#define IMG_W 768
#define IMG_C 3
#define IMG_HW (IMG_H * IMG_W)
#define ROW_F (IMG_W * IMG_C)          // 2304 floats per image row (mod 8 == 0)

// 256-bit global load (sm_100 family): 8 consecutive floats from a 32B-aligned ptr.
__device__ __forceinline__ void ldg256(const float* __restrict__ p, float r[8]) {
    unsigned a0, a1, a2, a3, a4, a5, a6, a7;
    asm("ld.global.nc.v8.b32 {%0,%1,%2,%3,%4,%5,%6,%7}, [%8];"
        : "=r"(a0), "=r"(a1), "=r"(a2), "=r"(a3),
          "=r"(a4), "=r"(a5), "=r"(a6), "=r"(a7)
        : "l"(p));
    r[0] = __uint_as_float(a0); r[1] = __uint_as_float(a1);
    r[2] = __uint_as_float(a2); r[3] = __uint_as_float(a3);
    r[4] = __uint_as_float(a4); r[5] = __uint_as_float(a5);
    r[6] = __uint_as_float(a6); r[7] = __uint_as_float(a7);
}

// branchless 4-way select by o in {0,1,2,3}
__device__ __forceinline__ float sel4(float a, float b, float c, float d, int o) {
    float r = (o == 1) ? b : a;
    r = (o == 2) ? c : r;
    r = (o == 3) ? d : r;
    return r;
}

__global__ __launch_bounds__(256) void warp_kernel(
    const float* __restrict__ image,
    const float* __restrict__ flow,
    float* __restrict__ out)
{
    __shared__ float sbuf[256 * 3];     // 3 KB staging for coalesced stores

    int tid = threadIdx.x;
    int idx = blockIdx.x * 256 + tid;   // one pixel per thread, grid is exact

    int b   = idx / IMG_HW;
    int rem = idx - b * IMG_HW;
    int y   = rem / IMG_W;
    int x   = rem - y * IMG_W;

    float2 f = __ldg((const float2*)flow + idx);   // coalesced LDG.64
    float qy = (float)y - f.x;
    float qx = (float)x - f.y;

    float y0f = fminf(fmaxf(floorf(qy), 0.0f), (float)(IMG_H - 2));
    float x0f = fminf(fmaxf(floorf(qx), 0.0f), (float)(IMG_W - 2));
    float ay  = fminf(fmaxf(qy - y0f, 0.0f), 1.0f);
    float ax  = fminf(fmaxf(qx - x0f, 0.0f), 1.0f);

    int yi = (int)y0f;
    int xi = (int)x0f;

    const float* imgb = image + (size_t)b * (IMG_HW * IMG_C);
    int af = (yi * IMG_W + xi) * IMG_C;   // float offset of top-left sample
    int o8 = af & 7;                      // phase within 32B window (rows share it)

    const float* pt = imgb + (af & ~7);   // 32B-aligned top window
    const float* pb = pt + ROW_F;         // bottom window, same phase

    float t[13], bo[13];
    ldg256(pt, t);                        // floats 0..7  (one request)
    ldg256(pb, bo);

    t[8] = t[9] = t[10] = t[11] = 0.0f;
    bo[8] = bo[9] = bo[10] = bo[11] = 0.0f;
    if (o8 >= 3) {                        // predicated tail: floats 8..11
        float4 tt = __ldg((const float4*)(pt + 8));
        float4 bb = __ldg((const float4*)(pb + 8));
        t[8] = tt.x;  t[9] = tt.y;  t[10] = tt.z;  t[11] = tt.w;
        bo[8] = bb.x; bo[9] = bb.y; bo[10] = bb.z; bo[11] = bb.w;
    }
    t[12] = bo[12] = 0.0f;
    if (o8 == 7) {                        // rare: span needs float 12 (in-bounds)
        t[12]  = __ldg(pt + 12);
        bo[12] = __ldg(pb + 12);
    }

    // vertical lerp across the 13-float window
    float m[13];
    #pragma unroll
    for (int j = 0; j < 13; j++)
        m[j] = t[j] + ay * (bo[j] - t[j]);

    // stage 1: shift window by 4 if o8 >= 4
    float u[9];
    bool hi = (o8 >= 4);
    #pragma unroll
    for (int j = 0; j < 9; j++)
        u[j] = hi ? m[j + 4] : m[j];

    // stage 2: select span floats u[o2 + c] / u[o2 + 3 + c], horizontal lerp
    int o2 = o8 & 3;
    float l0 = sel4(u[0], u[1], u[2], u[3], o2);
    float l1 = sel4(u[1], u[2], u[3], u[4], o2);
    float l2 = sel4(u[2], u[3], u[4], u[5], o2);
    float r0 = sel4(u[3], u[4], u[5], u[6], o2);
    float r1 = sel4(u[4], u[5], u[6], u[7], o2);
    float r2 = sel4(u[5], u[6], u[7], u[8], o2);

    sbuf[tid * 3 + 0] = l0 + ax * (r0 - l0);   // conflict-free (gcd(3,32)=1)
    sbuf[tid * 3 + 1] = l1 + ax * (r1 - l1);
    sbuf[tid * 3 + 2] = l2 + ax * (r2 - l2);

    __syncthreads();

    // 256 px * 12B = 3072B = 192 float4, perfectly coalesced
    if (tid < 192) {
        float4* ob = (float4*)(out + (size_t)blockIdx.x * (256 * 3));
        ob[tid] = ((const float4*)sbuf)[tid];
    }
}

extern "C" void kernel_launch(void* const* d_in, const int* in_sizes, int n_in,
                              void* d_out, int out_size) {
    const float* image = (const float*)d_in[0];
    const float* flow  = (const float*)d_in[1];
    float* out = (float*)d_out;

    int npix   = in_sizes[1] / 2;        // 18,874,368 — divisible by 256
    int blocks = npix / 256;             // 73728, no tail
    warp_kernel<<<blocks, 256>>>(image, flow, out);
}